// round 2
// baseline (speedup 1.0000x reference)
#include <cuda_runtime.h>

// VectorQuantizer: inputs [32,64,64,64] f32 (NCHW), weight [512,64] f32.
// out[0 .. N*D)   = q_st = fl(x + fl(q - x)) in NCHW
// out[N*D .. end) = loss = 1.25 * mean((q - x)^2)
//
// Argmin must bit-match the reference's fp32 computation:
//   d_k = fl( fl(Sx + Sw_k) - fl(2 * dot_k) ),  argmin first-index on ties.
// Sx computed SEQUENTIALLY over c (hypothesis: XLA CPU reduce order), with
// squares rounded to fp32 before summation (flat**2 is materialized).

#define KCODES 512
#define DDIM   64
#define HWSZ   4096
#define NBATCH 32
#define NTOT   (NBATCH * HWSZ)   // 131072
#define NTHREADS 512
#define NCTAS  (NTOT / NTHREADS) // 256

typedef unsigned long long ull;

__device__ float g_partials[NCTAS];

__device__ __forceinline__ ull ffma2(ull a, ull b, ull c) {
    ull d;
    asm("fma.rn.f32x2 %0, %1, %2, %3;" : "=l"(d) : "l"(a), "l"(b), "l"(c));
    return d;
}
__device__ __forceinline__ ull fadd2(ull a, ull b) {
    ull d;
    asm("add.rn.f32x2 %0, %1, %2;" : "=l"(d) : "l"(a), "l"(b));
    return d;
}
__device__ __forceinline__ ull pack2(float lo, float hi) {
    ull d;
    asm("mov.b64 %0, {%1, %2};" : "=l"(d) : "f"(lo), "f"(hi));
    return d;
}
__device__ __forceinline__ void unpack2(ull v, float& lo, float& hi) {
    asm("mov.b64 {%0, %1}, %2;" : "=f"(lo), "=f"(hi) : "l"(v));
}

extern __shared__ float smem[];   // [0..K*D) codebook, [K*D..K*D+K) norms

__global__ void __launch_bounds__(NTHREADS, 1)
vq_kernel(const float* __restrict__ input,
          const float* __restrict__ weight,
          float* __restrict__ out)
{
    float* sw  = smem;                 // 512*64 f32 = 128 KB
    float* swn = smem + KCODES * DDIM; // 512 f32

    const int tid = threadIdx.x;

    // ---- stage codebook into smem ----
    {
        const float4* wg  = reinterpret_cast<const float4*>(weight);
        float4*       wsv = reinterpret_cast<float4*>(sw);
        #pragma unroll
        for (int i = tid; i < KCODES * DDIM / 4; i += NTHREADS)
            wsv[i] = wg[i];
    }
    __syncthreads();

    // ---- codebook norms: sequential, rounded squares (order irrelevant at
    //      this magnitude, but match the literal formula anyway) ----
    {
        const float* row = sw + tid * DDIM;
        float s = 0.f;
        #pragma unroll
        for (int c = 0; c < DDIM; c++)
            s = __fadd_rn(s, __fmul_rn(row[c], row[c]));
        swn[tid] = s;
    }
    __syncthreads();

    // ---- load this thread's vector (strided NCHW) ----
    const int n  = blockIdx.x * NTHREADS + tid;
    const int b  = n >> 12;
    const int hw = n & (HWSZ - 1);
    const float* xp = input + (size_t)b * DDIM * HWSZ + hw;

    float xr[DDIM];
    #pragma unroll
    for (int c = 0; c < DDIM; c++)
        xr[c] = xp[(size_t)c * HWSZ];

    // ---- Sx: SEQUENTIAL fp32 sum of rounded squares (bit-exact hypothesis) ----
    float sx = 0.f;
    #pragma unroll
    for (int c = 0; c < DDIM; c++)
        sx = __fadd_rn(sx, __fmul_rn(xr[c], xr[c]));

    // pack x into f32x2 for the dot pipeline
    ull x2[DDIM / 2];
    #pragma unroll
    for (int j = 0; j < DDIM / 2; j++)
        x2[j] = pack2(xr[2 * j], xr[2 * j + 1]);

    // ---- argmin over K: d = fl( fl(Sx + Sw_k) - fl(2*dot) ), first-index ties ----
    float best = 3.4e38f;
    int   bidx = 0;
    const ull* wp = reinterpret_cast<const ull*>(sw);

    #pragma unroll 2
    for (int k = 0; k < KCODES; k++) {
        const ull* row = wp + k * (DDIM / 2);
        ull a0 = 0ull, a1 = 0ull, a2 = 0ull, a3 = 0ull;
        #pragma unroll
        for (int j = 0; j < DDIM / 2; j += 4) {
            a0 = ffma2(x2[j + 0], row[j + 0], a0);
            a1 = ffma2(x2[j + 1], row[j + 1], a1);
            a2 = ffma2(x2[j + 2], row[j + 2], a2);
            a3 = ffma2(x2[j + 3], row[j + 3], a3);
        }
        a0 = fadd2(a0, a1);
        a2 = fadd2(a2, a3);
        a0 = fadd2(a0, a2);
        float lo, hi;
        unpack2(a0, lo, hi);
        float dot = __fadd_rn(lo, hi);
        // exact replication of reference expression tree:
        float t = __fadd_rn(sx, swn[k]);
        float d = __fsub_rn(t, __fmul_rn(2.0f, dot));
        if (d < best) { best = d; bidx = k; }
    }

    // ---- gather, straight-through output q_st = fl(x + fl(q - x)), loss ----
    const float* qrow = sw + bidx * DDIM;
    float* outp = out + (size_t)b * DDIM * HWSZ + hw;
    float lloss = 0.f;
    #pragma unroll
    for (int c = 0; c < DDIM; c++) {
        float q = qrow[c];
        float x = xr[c];
        float e = __fsub_rn(q, x);
        outp[(size_t)c * HWSZ] = __fadd_rn(x, e);
        lloss = fmaf(e, e, lloss);
    }

    // ---- deterministic block reduction of loss (reuse smem) ----
    __syncthreads();
    sw[tid] = lloss;
    __syncthreads();
    #pragma unroll
    for (int s = NTHREADS / 2; s > 0; s >>= 1) {
        if (tid < s) sw[tid] += sw[tid + s];
        __syncthreads();
    }
    if (tid == 0) g_partials[blockIdx.x] = sw[0];
}

__global__ void loss_kernel(float* __restrict__ out, int out_size)
{
    __shared__ float red[256];
    const int tid = threadIdx.x;
    float s = 0.f;
    for (int i = tid; i < NCTAS; i += 256) s += g_partials[i];
    red[tid] = s;
    __syncthreads();
    #pragma unroll
    for (int st = 128; st > 0; st >>= 1) {
        if (tid < st) red[tid] += red[tid + st];
        __syncthreads();
    }
    if (tid == 0) {
        float loss = red[0] * 1.25f / (float)((long long)NTOT * DDIM);
        for (long long i = (long long)NTOT * DDIM; i < out_size; i++)
            out[i] = loss;
    }
}

extern "C" void kernel_launch(void* const* d_in, const int* in_sizes, int n_in,
                              void* d_out, int out_size)
{
    const float* input  = (const float*)d_in[0];
    const float* weight = (const float*)d_in[1];
    float* out = (float*)d_out;

    const int smem_bytes = (KCODES * DDIM + KCODES) * (int)sizeof(float);
    cudaFuncSetAttribute(vq_kernel, cudaFuncAttributeMaxDynamicSharedMemorySize, smem_bytes);

    vq_kernel<<<NCTAS, NTHREADS, smem_bytes>>>(input, weight, out);
    loss_kernel<<<1, 256>>>(out, out_size);
}